// round 3
// baseline (speedup 1.0000x reference)
#include <cuda_runtime.h>
#include <cuda.h>
#include <cstdint>

#define NE 16
#define NT 512
#define NH 2048
#define NI 4096

// 134MB activation scratch (allocation-free rule: __device__ global)
__device__ __align__(1024) float g_act[(size_t)NE * NT * NI];

// ---------------- device helpers ----------------
__device__ __forceinline__ uint32_t smem_u32(const void* p) {
    uint32_t a;
    asm("{ .reg .u64 t; cvta.to.shared.u64 t, %1; cvt.u32.u64 %0, t; }" : "=r"(a) : "l"(p));
    return a;
}

#define MBAR_INIT(addr, cnt) \
    asm volatile("mbarrier.init.shared.b64 [%0], %1;" :: "r"(addr), "r"(cnt) : "memory")
#define MBAR_EXPECT_TX(addr, bytes) \
    asm volatile("mbarrier.arrive.expect_tx.shared.b64 _, [%0], %1;" :: "r"(addr), "r"(bytes) : "memory")
#define MBAR_ARRIVE(addr) \
    asm volatile("mbarrier.arrive.shared.b64 _, [%0];" :: "r"(addr) : "memory")
#define WAIT_PAR(addr, ph) do {                                                  \
    uint32_t _a = (addr), _p = (ph);                                             \
    asm volatile("{\n\t.reg .pred P;\n\t"                                        \
                 "WL_%=:\n\t"                                                    \
                 "mbarrier.try_wait.parity.shared.b64 P, [%0], %1, 0x989680;\n\t"\
                 "@!P bra WL_%=;\n\t}" :: "r"(_a), "r"(_p) : "memory");          \
} while (0)

#define TMA2D(smem, map, x, y, mbar)                                                          \
    asm volatile("cp.async.bulk.tensor.2d.shared::cta.global.tile.mbarrier::complete_tx::bytes " \
                 "[%0], [%1, {%2, %3}], [%4];"                                                \
                 :: "r"(smem), "l"(map), "r"(x), "r"(y), "r"(mbar) : "memory")

// ld.shared.f32 + round-to-nearest tf32
__device__ __forceinline__ uint32_t lds_tf32(uint32_t addr) {
    uint32_t v;
    asm volatile("{\n\t.reg .f32 f;\n\tld.shared.f32 f, [%1];\n\tcvt.rna.tf32.f32 %0, f;\n\t}"
                 : "=r"(v) : "r"(addr));
    return v;
}

#define MMA_TF32(c, a0, a1, a2, a3, b0, b1)                                      \
    asm volatile("mma.sync.aligned.m16n8k8.row.col.f32.tf32.tf32.f32 "           \
                 "{%0,%1,%2,%3}, {%4,%5,%6,%7}, {%8,%9}, {%0,%1,%2,%3};"         \
                 : "+f"((c)[0]), "+f"((c)[1]), "+f"((c)[2]), "+f"((c)[3])        \
                 : "r"(a0), "r"(a1), "r"(a2), "r"(a3), "r"(b0), "r"(b1))

static constexpr uint32_t STAGES = 4;
static constexpr uint32_t STAGE_BYTES = 49152;
static constexpr uint32_t SMEM_ASK = STAGES * STAGE_BYTES + 1024;

// ============================================================================
// GEMM1: act = up * silu(gate). CTA = 128 tokens x 128 act-cols.
// 16 warps: warps 0-7 compute gate (warp tile 64x32), warps 8-15 compute up.
// SwiGLU fused via padded smem exchange after the mainloop.
// ============================================================================
__global__ void __launch_bounds__(512, 1) moe_gemm1(
    const __grid_constant__ CUtensorMap tmA,
    const __grid_constant__ CUtensorMap tmB) {
    extern __shared__ __align__(16) char dsm[];
    uint32_t base = (smem_u32(dsm) + 1023u) & ~1023u;
    uint32_t fullb = base + STAGES * STAGE_BYTES;   // 4 x 8B
    uint32_t emptb = fullb + 64;                    // 4 x 8B

    int tid = threadIdx.x, wid = tid >> 5, lane = tid & 31;
    int g = lane >> 2, tig = lane & 3;
    int isup = wid >> 3;            // 0 = gate warps, 1 = up warps
    int wsub = wid & 7;
    int wm = wsub >> 2, wn = wsub & 3;   // warp tile 64x32 over 128x128
    uint32_t xr = (uint32_t)g << 4;

    int b = blockIdx.x;
    int mt = b & 3, nt = (b >> 2) & 31, e = b >> 7;
    int arow = e * NT + mt * 128;
    int grow = e * (2 * NI) + nt * 128;
    int urow = grow + NI;

    if (tid == 0) {
        for (int s = 0; s < 4; s++) { MBAR_INIT(fullb + 8 * s, 1); MBAR_INIT(emptb + 8 * s, 16); }
        asm volatile("fence.proxy.async.shared::cta;" ::: "memory");
    }
    __syncthreads();

    if (tid == 0) {
        for (int c = 0; c < 4; c++) {
            uint32_t sb = base + (uint32_t)c * STAGE_BYTES;
            MBAR_EXPECT_TX(fullb + 8 * c, STAGE_BYTES);
            TMA2D(sb,         &tmA, c * 32, arow, fullb + 8 * c);
            TMA2D(sb + 16384, &tmB, c * 32, grow, fullb + 8 * c);
            TMA2D(sb + 32768, &tmB, c * 32, urow, fullb + 8 * c);
        }
    }

    float acc[4][4][4];
    #pragma unroll
    for (int i = 0; i < 4; i++)
        #pragma unroll
        for (int j = 0; j < 4; j++)
            #pragma unroll
            for (int q = 0; q < 4; q++) acc[i][j][q] = 0.f;

    uint32_t rowA[4];
    #pragma unroll
    for (int mi = 0; mi < 4; mi++) rowA[mi] = (uint32_t)(wm * 64 + mi * 16 + g) * 128;
    uint32_t rowB = (uint32_t)(wn * 32 + g) * 128;
    uint32_t bOff = isup ? 32768u : 16384u;   // gate warps read Bg, up warps Bu

    #pragma unroll 1
    for (int c = 0; c < 64; c++) {
        int s = c & 3, ph = (c >> 2) & 1;
        WAIT_PAR(fullb + 8 * s, ph);
        uint32_t sA = base + (uint32_t)s * STAGE_BYTES;
        uint32_t sB = sA + bOff;

        #pragma unroll
        for (int kk = 0; kk < 4; kk++) {
            uint32_t c0 = (((uint32_t)(kk * 8 + tig)) * 4) ^ xr;
            uint32_t c1 = (((uint32_t)(kk * 8 + tig + 4)) * 4) ^ xr;
            uint32_t a[4][4];
            #pragma unroll
            for (int mi = 0; mi < 4; mi++) {
                a[mi][0] = lds_tf32(sA + rowA[mi] + c0);
                a[mi][1] = lds_tf32(sA + rowA[mi] + 1024 + c0);
                a[mi][2] = lds_tf32(sA + rowA[mi] + c1);
                a[mi][3] = lds_tf32(sA + rowA[mi] + 1024 + c1);
            }
            #pragma unroll
            for (int nj = 0; nj < 4; nj++) {
                uint32_t roff = (uint32_t)nj * 1024;
                uint32_t b0 = lds_tf32(sB + rowB + roff + c0);
                uint32_t b1 = lds_tf32(sB + rowB + roff + c1);
                #pragma unroll
                for (int mi = 0; mi < 4; mi++)
                    MMA_TF32(acc[mi][nj], a[mi][0], a[mi][1], a[mi][2], a[mi][3], b0, b1);
            }
        }
        if (lane == 0) MBAR_ARRIVE(emptb + 8 * s);
        if (tid == 0 && c < 60) {
            WAIT_PAR(emptb + 8 * s, ph);
            uint32_t sb = base + (uint32_t)s * STAGE_BYTES;
            MBAR_EXPECT_TX(fullb + 8 * s, STAGE_BYTES);
            TMA2D(sb,         &tmA, (c + 4) * 32, arow, fullb + 8 * s);
            TMA2D(sb + 16384, &tmB, (c + 4) * 32, grow, fullb + 8 * s);
            TMA2D(sb + 32768, &tmB, (c + 4) * 32, urow, fullb + 8 * s);
        }
    }

    // Epilogue: gate warps -> silu(gate) into padded smem; up warps multiply.
    const uint32_t PITCH = 132;  // floats, pad to break bank conflicts
    __syncthreads();             // all stages consumed; reuse stage smem
    if (!isup) {
        #pragma unroll
        for (int mi = 0; mi < 4; mi++) {
            uint32_t r0 = (uint32_t)(wm * 64 + mi * 16 + g);
            #pragma unroll
            for (int nj = 0; nj < 4; nj++) {
                uint32_t col = (uint32_t)(wn * 32 + nj * 8 + 2 * tig);
                float2 v0, v1;
                float gg = acc[mi][nj][0];
                v0.x = gg / (1.0f + __expf(-gg));
                gg = acc[mi][nj][1];
                v0.y = gg / (1.0f + __expf(-gg));
                gg = acc[mi][nj][2];
                v1.x = gg / (1.0f + __expf(-gg));
                gg = acc[mi][nj][3];
                v1.y = gg / (1.0f + __expf(-gg));
                *reinterpret_cast<float2*>(dsm + (size_t)(base - smem_u32(dsm)) +
                                           (size_t)(r0 * PITCH + col) * 4) = v0;
                *reinterpret_cast<float2*>(dsm + (size_t)(base - smem_u32(dsm)) +
                                           (size_t)((r0 + 8) * PITCH + col) * 4) = v1;
            }
        }
    }
    __syncthreads();
    if (isup) {
        char* exb = dsm + (size_t)(base - smem_u32(dsm));
        #pragma unroll
        for (int mi = 0; mi < 4; mi++) {
            uint32_t r0 = (uint32_t)(wm * 64 + mi * 16 + g);
            int tok0 = mt * 128 + (int)r0;
            float* p0 = g_act + (size_t)(e * NT + tok0) * NI + nt * 128 + wn * 32;
            float* p1 = p0 + (size_t)8 * NI;
            #pragma unroll
            for (int nj = 0; nj < 4; nj++) {
                uint32_t col = (uint32_t)(wn * 32 + nj * 8 + 2 * tig);
                float2 s0 = *reinterpret_cast<float2*>(exb + (size_t)(r0 * PITCH + col) * 4);
                float2 s1 = *reinterpret_cast<float2*>(exb + (size_t)((r0 + 8) * PITCH + col) * 4);
                float2 v0, v1;
                v0.x = acc[mi][nj][0] * s0.x;
                v0.y = acc[mi][nj][1] * s0.y;
                v1.x = acc[mi][nj][2] * s1.x;
                v1.y = acc[mi][nj][3] * s1.y;
                int colo = nj * 8 + 2 * tig;
                *reinterpret_cast<float2*>(p0 + colo) = v0;
                *reinterpret_cast<float2*>(p1 + colo) = v1;
            }
        }
    }
}

// ============================================================================
// GEMM2: out = act @ W2^T. CTA 128 x 256, 16 warps, warp tile 64x32. K = 4096.
// ============================================================================
__global__ void __launch_bounds__(512, 1) moe_gemm2(
    const __grid_constant__ CUtensorMap tmA,
    const __grid_constant__ CUtensorMap tmB,
    float* __restrict__ out) {
    extern __shared__ __align__(16) char dsm[];
    uint32_t base = (smem_u32(dsm) + 1023u) & ~1023u;
    uint32_t fullb = base + STAGES * STAGE_BYTES;
    uint32_t emptb = fullb + 64;

    int tid = threadIdx.x, wid = tid >> 5, lane = tid & 31;
    int g = lane >> 2, tig = lane & 3;
    int wm = wid >> 3, wn = wid & 7;     // 2 x 8 warps, tile 64x32 over 128x256
    uint32_t xr = (uint32_t)g << 4;

    int b = blockIdx.x;
    int mt = b & 3, nt = (b >> 2) & 7, e = b >> 5;
    int arow = e * NT + mt * 128;
    int brow = e * NH + nt * 256;

    if (tid == 0) {
        for (int s = 0; s < 4; s++) { MBAR_INIT(fullb + 8 * s, 1); MBAR_INIT(emptb + 8 * s, 16); }
        asm volatile("fence.proxy.async.shared::cta;" ::: "memory");
    }
    __syncthreads();

    if (tid == 0) {
        for (int c = 0; c < 4; c++) {
            uint32_t sb = base + (uint32_t)c * STAGE_BYTES;
            MBAR_EXPECT_TX(fullb + 8 * c, STAGE_BYTES);
            TMA2D(sb,         &tmA, c * 32, arow, fullb + 8 * c);
            TMA2D(sb + 16384, &tmB, c * 32, brow, fullb + 8 * c);  // box [32,256] = 32KB
        }
    }

    float acc[4][4][4];
    #pragma unroll
    for (int i = 0; i < 4; i++)
        #pragma unroll
        for (int j = 0; j < 4; j++)
            #pragma unroll
            for (int q = 0; q < 4; q++) acc[i][j][q] = 0.f;

    uint32_t rowA[4];
    #pragma unroll
    for (int mi = 0; mi < 4; mi++) rowA[mi] = (uint32_t)(wm * 64 + mi * 16 + g) * 128;
    uint32_t rowB = (uint32_t)(wn * 32 + g) * 128;

    #pragma unroll 1
    for (int c = 0; c < 128; c++) {
        int s = c & 3, ph = (c >> 2) & 1;
        WAIT_PAR(fullb + 8 * s, ph);
        uint32_t sA = base + (uint32_t)s * STAGE_BYTES;
        uint32_t sB = sA + 16384;

        #pragma unroll
        for (int kk = 0; kk < 4; kk++) {
            uint32_t c0 = (((uint32_t)(kk * 8 + tig)) * 4) ^ xr;
            uint32_t c1 = (((uint32_t)(kk * 8 + tig + 4)) * 4) ^ xr;
            uint32_t a[4][4];
            #pragma unroll
            for (int mi = 0; mi < 4; mi++) {
                a[mi][0] = lds_tf32(sA + rowA[mi] + c0);
                a[mi][1] = lds_tf32(sA + rowA[mi] + 1024 + c0);
                a[mi][2] = lds_tf32(sA + rowA[mi] + c1);
                a[mi][3] = lds_tf32(sA + rowA[mi] + 1024 + c1);
            }
            #pragma unroll
            for (int nj = 0; nj < 4; nj++) {
                uint32_t roff = (uint32_t)nj * 1024;
                uint32_t b0 = lds_tf32(sB + rowB + roff + c0);
                uint32_t b1 = lds_tf32(sB + rowB + roff + c1);
                #pragma unroll
                for (int mi = 0; mi < 4; mi++)
                    MMA_TF32(acc[mi][nj], a[mi][0], a[mi][1], a[mi][2], a[mi][3], b0, b1);
            }
        }
        if (lane == 0) MBAR_ARRIVE(emptb + 8 * s);
        if (tid == 0 && c < 124) {
            WAIT_PAR(emptb + 8 * s, ph);
            uint32_t sb = base + (uint32_t)s * STAGE_BYTES;
            MBAR_EXPECT_TX(fullb + 8 * s, STAGE_BYTES);
            TMA2D(sb,         &tmA, (c + 4) * 32, arow, fullb + 8 * s);
            TMA2D(sb + 16384, &tmB, (c + 4) * 32, brow, fullb + 8 * s);
        }
    }

    #pragma unroll
    for (int mi = 0; mi < 4; mi++) {
        int tok0 = mt * 128 + wm * 64 + mi * 16 + g;
        float* p0 = out + (size_t)(e * NT + tok0) * NH + nt * 256 + wn * 32;
        float* p1 = p0 + (size_t)8 * NH;
        #pragma unroll
        for (int nj = 0; nj < 4; nj++) {
            int colo = nj * 8 + 2 * tig;
            float2 v0 = {acc[mi][nj][0], acc[mi][nj][1]};
            float2 v1 = {acc[mi][nj][2], acc[mi][nj][3]};
            *reinterpret_cast<float2*>(p0 + colo) = v0;
            *reinterpret_cast<float2*>(p1 + colo) = v1;
        }
    }
}

// ============================================================================
// Host
// ============================================================================
typedef CUresult (*EncodeFn)(CUtensorMap*, CUtensorMapDataType, cuuint32_t, void*,
                             const cuuint64_t*, const cuuint64_t*, const cuuint32_t*,
                             const cuuint32_t*, CUtensorMapInterleave, CUtensorMapSwizzle,
                             CUtensorMapL2promotion, CUtensorMapFloatOOBfill);

static void encode2d(EncodeFn fn, CUtensorMap* m, void* p,
                     uint64_t d0, uint64_t d1, uint64_t stride_bytes,
                     uint32_t b0, uint32_t b1) {
    cuuint64_t dims[2] = {d0, d1};
    cuuint64_t st[1]   = {stride_bytes};
    cuuint32_t box[2]  = {b0, b1};
    cuuint32_t es[2]   = {1, 1};
    fn(m, CU_TENSOR_MAP_DATA_TYPE_FLOAT32, 2, p, dims, st, box, es,
       CU_TENSOR_MAP_INTERLEAVE_NONE, CU_TENSOR_MAP_SWIZZLE_128B,
       CU_TENSOR_MAP_L2_PROMOTION_L2_128B, CU_TENSOR_MAP_FLOAT_OOB_FILL_NONE);
}

extern "C" void kernel_launch(void* const* d_in, const int* in_sizes, int n_in,
                              void* d_out, int out_size) {
    void* X  = d_in[0];  // (E*T, H) fp32
    void* W1 = d_in[1];  // (E, 2I, H) fp32
    void* W2 = d_in[2];  // (E, H, I) fp32

    void* pfn = nullptr;
    cudaDriverEntryPointQueryResult qr;
#if CUDART_VERSION >= 12050
    cudaGetDriverEntryPointByVersion("cuTensorMapEncodeTiled", &pfn, 12000,
                                     cudaEnableDefault, &qr);
#else
    cudaGetDriverEntryPoint("cuTensorMapEncodeTiled", &pfn, cudaEnableDefault, &qr);
#endif
    EncodeFn enc = (EncodeFn)pfn;

    void* actp = nullptr;
    cudaGetSymbolAddress(&actp, g_act);

    CUtensorMap tA, tB, tA2, tB2;
    encode2d(enc, &tA,  X,    NH, (uint64_t)NE * NT,     (uint64_t)NH * 4, 32, 128);
    encode2d(enc, &tB,  W1,   NH, (uint64_t)NE * 2 * NI, (uint64_t)NH * 4, 32, 128);
    encode2d(enc, &tA2, actp, NI, (uint64_t)NE * NT,     (uint64_t)NI * 4, 32, 128);
    encode2d(enc, &tB2, W2,   NI, (uint64_t)NE * NH,     (uint64_t)NI * 4, 32, 256);

    cudaFuncSetAttribute(moe_gemm1, cudaFuncAttributeMaxDynamicSharedMemorySize, SMEM_ASK);
    cudaFuncSetAttribute(moe_gemm2, cudaFuncAttributeMaxDynamicSharedMemorySize, SMEM_ASK);

    moe_gemm1<<<NE * 4 * 32, 512, SMEM_ASK>>>(tA, tB);
    moe_gemm2<<<NE * 4 * 8, 512, SMEM_ASK>>>(tA2, tB2, (float*)d_out);
}

// round 4
// speedup vs baseline: 1.1215x; 1.1215x over previous
#include <cuda_runtime.h>
#include <cuda.h>
#include <cstdint>

#define NE 16
#define NT 512
#define NH 2048
#define NI 4096

// 134MB activation scratch (allocation-free rule: __device__ global)
__device__ __align__(1024) float g_act[(size_t)NE * NT * NI];

// ---------------- device helpers ----------------
__device__ __forceinline__ uint32_t smem_u32(const void* p) {
    uint32_t a;
    asm("{ .reg .u64 t; cvta.to.shared.u64 t, %1; cvt.u32.u64 %0, t; }" : "=r"(a) : "l"(p));
    return a;
}

#define MBAR_INIT(addr, cnt) \
    asm volatile("mbarrier.init.shared.b64 [%0], %1;" :: "r"(addr), "r"(cnt) : "memory")
#define MBAR_EXPECT_TX(addr, bytes) \
    asm volatile("mbarrier.arrive.expect_tx.shared.b64 _, [%0], %1;" :: "r"(addr), "r"(bytes) : "memory")
#define MBAR_ARRIVE(addr) \
    asm volatile("mbarrier.arrive.shared.b64 _, [%0];" :: "r"(addr) : "memory")
#define WAIT_PAR(addr, ph) do {                                                  \
    uint32_t _a = (addr), _p = (ph);                                             \
    asm volatile("{\n\t.reg .pred P;\n\t"                                        \
                 "WL_%=:\n\t"                                                    \
                 "mbarrier.try_wait.parity.shared.b64 P, [%0], %1, 0x989680;\n\t"\
                 "@!P bra WL_%=;\n\t}" :: "r"(_a), "r"(_p) : "memory");          \
} while (0)

#define TMA2D(smem, map, x, y, mbar)                                                          \
    asm volatile("cp.async.bulk.tensor.2d.shared::cta.global.tile.mbarrier::complete_tx::bytes " \
                 "[%0], [%1, {%2, %3}], [%4];"                                                \
                 :: "r"(smem), "l"(map), "r"(x), "r"(y), "r"(mbar) : "memory")

// ld.shared.f32 + round-to-nearest tf32
__device__ __forceinline__ uint32_t lds_tf32(uint32_t addr) {
    uint32_t v;
    asm volatile("{\n\t.reg .f32 f;\n\tld.shared.f32 f, [%1];\n\tcvt.rna.tf32.f32 %0, f;\n\t}"
                 : "=r"(v) : "r"(addr));
    return v;
}

#define MMA_TF32(c, a0, a1, a2, a3, b0, b1)                                      \
    asm volatile("mma.sync.aligned.m16n8k8.row.col.f32.tf32.tf32.f32 "           \
                 "{%0,%1,%2,%3}, {%4,%5,%6,%7}, {%8,%9}, {%0,%1,%2,%3};"         \
                 : "+f"((c)[0]), "+f"((c)[1]), "+f"((c)[2]), "+f"((c)[3])        \
                 : "r"(a0), "r"(a1), "r"(a2), "r"(a3), "r"(b0), "r"(b1))

static constexpr uint32_t STAGES = 4;
static constexpr uint32_t STAGE_BYTES = 49152;
static constexpr uint32_t SMEM_ASK = STAGES * STAGE_BYTES + 1024;

// ============================================================================
// GEMM2: out = act @ W2^T. CTA 128x256, 8 warps, warp tile 64x64. K = 4096.
// Software-pipelined: double-buffered fragments, load k8-chunk j+1 during
// MMAs of chunk j; empty-arrive right after the last LDS of a stage.
// ============================================================================
__global__ void __launch_bounds__(256, 1) moe_gemm2(
    const __grid_constant__ CUtensorMap tmA,
    const __grid_constant__ CUtensorMap tmB,
    float* __restrict__ out) {
    extern __shared__ __align__(16) char dsm[];
    uint32_t base = (smem_u32(dsm) + 1023u) & ~1023u;
    uint32_t fullb = base + STAGES * STAGE_BYTES;
    uint32_t emptb = fullb + 64;

    int tid = threadIdx.x, wid = tid >> 5, lane = tid & 31;
    int g = lane >> 2, tig = lane & 3;
    int wm = wid >> 2, wn = wid & 3;   // 2x4 warps, warp tile 64x64
    uint32_t xr = (uint32_t)g << 4;

    int b = blockIdx.x;
    int mt = b & 3, nt = (b >> 2) & 7, e = b >> 5;
    int arow = e * NT + mt * 128;
    int brow = e * NH + nt * 256;

    if (tid == 0) {
        for (int s = 0; s < 4; s++) { MBAR_INIT(fullb + 8 * s, 1); MBAR_INIT(emptb + 8 * s, 8); }
        asm volatile("fence.proxy.async.shared::cta;" ::: "memory");
    }
    __syncthreads();

    if (tid == 0) {
        for (int c = 0; c < 4; c++) {
            uint32_t sb = base + (uint32_t)c * STAGE_BYTES;
            MBAR_EXPECT_TX(fullb + 8 * c, STAGE_BYTES);
            TMA2D(sb,         &tmA, c * 32, arow, fullb + 8 * c);
            TMA2D(sb + 16384, &tmB, c * 32, brow, fullb + 8 * c);
        }
    }

    float acc[4][8][4];
    #pragma unroll
    for (int i = 0; i < 4; i++)
        #pragma unroll
        for (int j = 0; j < 8; j++)
            #pragma unroll
            for (int q = 0; q < 4; q++) acc[i][j][q] = 0.f;

    uint32_t rowA[4];
    #pragma unroll
    for (int mi = 0; mi < 4; mi++) rowA[mi] = (uint32_t)(wm * 64 + mi * 16 + g) * 128;
    uint32_t rowB = (uint32_t)(wn * 64 + g) * 128;

    uint32_t fa[2][16], fb[2][16];

    // fragment load: k8-chunk kkL (0..3) of the stage at smem sA
    #define LOADF(buf, sA, kkL) do {                                             \
        uint32_t _s = (sA);                                                      \
        uint32_t c0 = (((uint32_t)((kkL) * 8 + tig)) * 4) ^ xr;                  \
        uint32_t c1 = (((uint32_t)((kkL) * 8 + tig + 4)) * 4) ^ xr;              \
        _Pragma("unroll")                                                        \
        for (int mi = 0; mi < 4; mi++) {                                         \
            fa[buf][mi * 4 + 0] = lds_tf32(_s + rowA[mi] + c0);                  \
            fa[buf][mi * 4 + 1] = lds_tf32(_s + rowA[mi] + 1024 + c0);           \
            fa[buf][mi * 4 + 2] = lds_tf32(_s + rowA[mi] + c1);                  \
            fa[buf][mi * 4 + 3] = lds_tf32(_s + rowA[mi] + 1024 + c1);           \
        }                                                                        \
        uint32_t _sb = _s + 16384 + rowB;                                        \
        _Pragma("unroll")                                                        \
        for (int nj = 0; nj < 8; nj++) {                                         \
            fb[buf][nj * 2 + 0] = lds_tf32(_sb + (uint32_t)nj * 1024 + c0);      \
            fb[buf][nj * 2 + 1] = lds_tf32(_sb + (uint32_t)nj * 1024 + c1);      \
        }                                                                        \
    } while (0)

    #define MMAS(buf) do {                                                       \
        _Pragma("unroll")                                                        \
        for (int nj = 0; nj < 8; nj++)                                           \
            _Pragma("unroll")                                                    \
            for (int mi = 0; mi < 4; mi++)                                       \
                MMA_TF32(acc[mi][nj], fa[buf][mi * 4 + 0], fa[buf][mi * 4 + 1],  \
                         fa[buf][mi * 4 + 2], fa[buf][mi * 4 + 3],               \
                         fb[buf][nj * 2 + 0], fb[buf][nj * 2 + 1]);              \
    } while (0)

    WAIT_PAR(fullb + 0, 0);
    {
        uint32_t sA0 = base;
        LOADF(0, sA0, 0);
    }
    #pragma unroll 1
    for (int ks = 0; ks < 128; ks++) {
        int s = ks & 3, ph = (ks >> 2) & 1;
        uint32_t sA = base + (uint32_t)s * STAGE_BYTES;
        // step 0: load kk1 -> buf1, mma buf0 (kk0)
        LOADF(1, sA, 1);
        MMAS(0);
        // step 1: load kk2 -> buf0, mma buf1 (kk1)
        LOADF(0, sA, 2);
        MMAS(1);
        // step 2: load kk3 -> buf1 (last LDS of stage), arrive empty, refill, mma buf0 (kk2)
        LOADF(1, sA, 3);
        if (lane == 0) MBAR_ARRIVE(emptb + 8 * s);
        if (tid == 0 && ks + 4 < 128) {
            WAIT_PAR(emptb + 8 * s, ph);
            MBAR_EXPECT_TX(fullb + 8 * s, STAGE_BYTES);
            TMA2D(sA,         &tmA, (ks + 4) * 32, arow, fullb + 8 * s);
            TMA2D(sA + 16384, &tmB, (ks + 4) * 32, brow, fullb + 8 * s);
        }
        MMAS(0);
        // step 3: mma buf1 (kk3), then wait+load next stage kk0 -> buf0
        MMAS(1);
        if (ks + 1 < 128) {
            int ns = ks + 1;
            WAIT_PAR(fullb + 8 * (ns & 3), (ns >> 2) & 1);
            uint32_t sN = base + (uint32_t)(ns & 3) * STAGE_BYTES;
            LOADF(0, sN, 0);
        }
    }
    #undef LOADF
    #undef MMAS

    #pragma unroll
    for (int mi = 0; mi < 4; mi++) {
        int tok0 = mt * 128 + wm * 64 + mi * 16 + g;
        float* p0 = out + (size_t)(e * NT + tok0) * NH + nt * 256 + wn * 64;
        float* p1 = p0 + (size_t)8 * NH;
        #pragma unroll
        for (int nj = 0; nj < 8; nj++) {
            int colo = nj * 8 + 2 * tig;
            float2 v0 = {acc[mi][nj][0], acc[mi][nj][1]};
            float2 v1 = {acc[mi][nj][2], acc[mi][nj][3]};
            *reinterpret_cast<float2*>(p0 + colo) = v0;
            *reinterpret_cast<float2*>(p1 + colo) = v1;
        }
    }
}

// ============================================================================
// GEMM1: act = up * silu(gate). CTA 128 tokens x 128 act-cols, 8 warps,
// warp tile 64 x (32 gate + 32 up). Same software pipeline as GEMM2.
// ============================================================================
__global__ void __launch_bounds__(256, 1) moe_gemm1(
    const __grid_constant__ CUtensorMap tmA,
    const __grid_constant__ CUtensorMap tmB) {
    extern __shared__ __align__(16) char dsm[];
    uint32_t base = (smem_u32(dsm) + 1023u) & ~1023u;
    uint32_t fullb = base + STAGES * STAGE_BYTES;
    uint32_t emptb = fullb + 64;

    int tid = threadIdx.x, wid = tid >> 5, lane = tid & 31;
    int g = lane >> 2, tig = lane & 3;
    int wm = wid >> 2, wn = wid & 3;
    uint32_t xr = (uint32_t)g << 4;

    int b = blockIdx.x;
    int mt = b & 3, nt = (b >> 2) & 31, e = b >> 7;
    int arow = e * NT + mt * 128;
    int grow = e * (2 * NI) + nt * 128;
    int urow = grow + NI;

    if (tid == 0) {
        for (int s = 0; s < 4; s++) { MBAR_INIT(fullb + 8 * s, 1); MBAR_INIT(emptb + 8 * s, 8); }
        asm volatile("fence.proxy.async.shared::cta;" ::: "memory");
    }
    __syncthreads();

    if (tid == 0) {
        for (int c = 0; c < 4; c++) {
            uint32_t sb = base + (uint32_t)c * STAGE_BYTES;
            MBAR_EXPECT_TX(fullb + 8 * c, STAGE_BYTES);
            TMA2D(sb,         &tmA, c * 32, arow, fullb + 8 * c);
            TMA2D(sb + 16384, &tmB, c * 32, grow, fullb + 8 * c);
            TMA2D(sb + 32768, &tmB, c * 32, urow, fullb + 8 * c);
        }
    }

    float accg[4][4][4], accu[4][4][4];
    #pragma unroll
    for (int i = 0; i < 4; i++)
        #pragma unroll
        for (int j = 0; j < 4; j++)
            #pragma unroll
            for (int q = 0; q < 4; q++) { accg[i][j][q] = 0.f; accu[i][j][q] = 0.f; }

    uint32_t rowA[4];
    #pragma unroll
    for (int mi = 0; mi < 4; mi++) rowA[mi] = (uint32_t)(wm * 64 + mi * 16 + g) * 128;
    uint32_t rowB = (uint32_t)(wn * 32 + g) * 128;

    uint32_t fa[2][16], fg[2][8], fu[2][8];

    #define LOADF1(buf, sA, kkL) do {                                            \
        uint32_t _s = (sA);                                                      \
        uint32_t c0 = (((uint32_t)((kkL) * 8 + tig)) * 4) ^ xr;                  \
        uint32_t c1 = (((uint32_t)((kkL) * 8 + tig + 4)) * 4) ^ xr;              \
        _Pragma("unroll")                                                        \
        for (int mi = 0; mi < 4; mi++) {                                         \
            fa[buf][mi * 4 + 0] = lds_tf32(_s + rowA[mi] + c0);                  \
            fa[buf][mi * 4 + 1] = lds_tf32(_s + rowA[mi] + 1024 + c0);           \
            fa[buf][mi * 4 + 2] = lds_tf32(_s + rowA[mi] + c1);                  \
            fa[buf][mi * 4 + 3] = lds_tf32(_s + rowA[mi] + 1024 + c1);           \
        }                                                                        \
        uint32_t _bg = _s + 16384 + rowB;                                        \
        uint32_t _bu = _s + 32768 + rowB;                                        \
        _Pragma("unroll")                                                        \
        for (int nj = 0; nj < 4; nj++) {                                         \
            fg[buf][nj * 2 + 0] = lds_tf32(_bg + (uint32_t)nj * 1024 + c0);      \
            fg[buf][nj * 2 + 1] = lds_tf32(_bg + (uint32_t)nj * 1024 + c1);      \
            fu[buf][nj * 2 + 0] = lds_tf32(_bu + (uint32_t)nj * 1024 + c0);      \
            fu[buf][nj * 2 + 1] = lds_tf32(_bu + (uint32_t)nj * 1024 + c1);      \
        }                                                                        \
    } while (0)

    #define MMAS1(buf) do {                                                      \
        _Pragma("unroll")                                                        \
        for (int nj = 0; nj < 4; nj++)                                           \
            _Pragma("unroll")                                                    \
            for (int mi = 0; mi < 4; mi++) {                                     \
                MMA_TF32(accg[mi][nj], fa[buf][mi * 4 + 0], fa[buf][mi * 4 + 1], \
                         fa[buf][mi * 4 + 2], fa[buf][mi * 4 + 3],               \
                         fg[buf][nj * 2 + 0], fg[buf][nj * 2 + 1]);              \
                MMA_TF32(accu[mi][nj], fa[buf][mi * 4 + 0], fa[buf][mi * 4 + 1], \
                         fa[buf][mi * 4 + 2], fa[buf][mi * 4 + 3],               \
                         fu[buf][nj * 2 + 0], fu[buf][nj * 2 + 1]);              \
            }                                                                    \
    } while (0)

    WAIT_PAR(fullb + 0, 0);
    LOADF1(0, base, 0);
    #pragma unroll 1
    for (int ks = 0; ks < 64; ks++) {
        int s = ks & 3, ph = (ks >> 2) & 1;
        uint32_t sA = base + (uint32_t)s * STAGE_BYTES;
        LOADF1(1, sA, 1);
        MMAS1(0);
        LOADF1(0, sA, 2);
        MMAS1(1);
        LOADF1(1, sA, 3);
        if (lane == 0) MBAR_ARRIVE(emptb + 8 * s);
        if (tid == 0 && ks + 4 < 64) {
            WAIT_PAR(emptb + 8 * s, ph);
            MBAR_EXPECT_TX(fullb + 8 * s, STAGE_BYTES);
            TMA2D(sA,         &tmA, (ks + 4) * 32, arow, fullb + 8 * s);
            TMA2D(sA + 16384, &tmB, (ks + 4) * 32, grow, fullb + 8 * s);
            TMA2D(sA + 32768, &tmB, (ks + 4) * 32, urow, fullb + 8 * s);
        }
        MMAS1(0);
        MMAS1(1);
        if (ks + 1 < 64) {
            int ns = ks + 1;
            WAIT_PAR(fullb + 8 * (ns & 3), (ns >> 2) & 1);
            uint32_t sN = base + (uint32_t)(ns & 3) * STAGE_BYTES;
            LOADF1(0, sN, 0);
        }
    }
    #undef LOADF1
    #undef MMAS1

    // Epilogue: SwiGLU in registers -> scratch
    #pragma unroll
    for (int mi = 0; mi < 4; mi++) {
        int tok0 = mt * 128 + wm * 64 + mi * 16 + g;
        float* p0 = g_act + (size_t)(e * NT + tok0) * NI + nt * 128 + wn * 32;
        float* p1 = p0 + (size_t)8 * NI;
        #pragma unroll
        for (int nj = 0; nj < 4; nj++) {
            int colo = nj * 8 + 2 * tig;
            float2 v0, v1;
            float gg = accg[mi][nj][0], uu = accu[mi][nj][0];
            v0.x = uu * gg / (1.0f + __expf(-gg));
            gg = accg[mi][nj][1]; uu = accu[mi][nj][1];
            v0.y = uu * gg / (1.0f + __expf(-gg));
            gg = accg[mi][nj][2]; uu = accu[mi][nj][2];
            v1.x = uu * gg / (1.0f + __expf(-gg));
            gg = accg[mi][nj][3]; uu = accu[mi][nj][3];
            v1.y = uu * gg / (1.0f + __expf(-gg));
            *reinterpret_cast<float2*>(p0 + colo) = v0;
            *reinterpret_cast<float2*>(p1 + colo) = v1;
        }
    }
}

// ============================================================================
// Host
// ============================================================================
typedef CUresult (*EncodeFn)(CUtensorMap*, CUtensorMapDataType, cuuint32_t, void*,
                             const cuuint64_t*, const cuuint64_t*, const cuuint32_t*,
                             const cuuint32_t*, CUtensorMapInterleave, CUtensorMapSwizzle,
                             CUtensorMapL2promotion, CUtensorMapFloatOOBfill);

static void encode2d(EncodeFn fn, CUtensorMap* m, void* p,
                     uint64_t d0, uint64_t d1, uint64_t stride_bytes,
                     uint32_t b0, uint32_t b1) {
    cuuint64_t dims[2] = {d0, d1};
    cuuint64_t st[1]   = {stride_bytes};
    cuuint32_t box[2]  = {b0, b1};
    cuuint32_t es[2]   = {1, 1};
    fn(m, CU_TENSOR_MAP_DATA_TYPE_FLOAT32, 2, p, dims, st, box, es,
       CU_TENSOR_MAP_INTERLEAVE_NONE, CU_TENSOR_MAP_SWIZZLE_128B,
       CU_TENSOR_MAP_L2_PROMOTION_L2_128B, CU_TENSOR_MAP_FLOAT_OOB_FILL_NONE);
}

extern "C" void kernel_launch(void* const* d_in, const int* in_sizes, int n_in,
                              void* d_out, int out_size) {
    void* X  = d_in[0];  // (E*T, H) fp32
    void* W1 = d_in[1];  // (E, 2I, H) fp32
    void* W2 = d_in[2];  // (E, H, I) fp32

    void* pfn = nullptr;
    cudaDriverEntryPointQueryResult qr;
#if CUDART_VERSION >= 12050
    cudaGetDriverEntryPointByVersion("cuTensorMapEncodeTiled", &pfn, 12000,
                                     cudaEnableDefault, &qr);
#else
    cudaGetDriverEntryPoint("cuTensorMapEncodeTiled", &pfn, cudaEnableDefault, &qr);
#endif
    EncodeFn enc = (EncodeFn)pfn;

    void* actp = nullptr;
    cudaGetSymbolAddress(&actp, g_act);

    CUtensorMap tA, tB, tA2, tB2;
    encode2d(enc, &tA,  X,    NH, (uint64_t)NE * NT,     (uint64_t)NH * 4, 32, 128);
    encode2d(enc, &tB,  W1,   NH, (uint64_t)NE * 2 * NI, (uint64_t)NH * 4, 32, 128);
    encode2d(enc, &tA2, actp, NI, (uint64_t)NE * NT,     (uint64_t)NI * 4, 32, 128);
    encode2d(enc, &tB2, W2,   NI, (uint64_t)NE * NH,     (uint64_t)NI * 4, 32, 256);

    cudaFuncSetAttribute(moe_gemm1, cudaFuncAttributeMaxDynamicSharedMemorySize, SMEM_ASK);
    cudaFuncSetAttribute(moe_gemm2, cudaFuncAttributeMaxDynamicSharedMemorySize, SMEM_ASK);

    moe_gemm1<<<NE * 4 * 32, 256, SMEM_ASK>>>(tA, tB);
    moe_gemm2<<<NE * 4 * 8, 256, SMEM_ASK>>>(tA2, tB2, (float*)d_out);
}

// round 5
// speedup vs baseline: 1.1760x; 1.0486x over previous
#include <cuda_runtime.h>
#include <cuda.h>
#include <cstdint>

#define NE 16
#define NT 512
#define NH 2048
#define NI 4096

// 134MB activation scratch (allocation-free rule: __device__ global)
__device__ __align__(1024) float g_act[(size_t)NE * NT * NI];

// ---------------- device helpers ----------------
__device__ __forceinline__ uint32_t smem_u32(const void* p) {
    uint32_t a;
    asm("{ .reg .u64 t; cvta.to.shared.u64 t, %1; cvt.u32.u64 %0, t; }" : "=r"(a) : "l"(p));
    return a;
}

#define MBAR_INIT(addr, cnt) \
    asm volatile("mbarrier.init.shared.b64 [%0], %1;" :: "r"(addr), "r"(cnt) : "memory")
#define MBAR_EXPECT_TX(addr, bytes) \
    asm volatile("mbarrier.arrive.expect_tx.shared.b64 _, [%0], %1;" :: "r"(addr), "r"(bytes) : "memory")
#define MBAR_ARRIVE(addr) \
    asm volatile("mbarrier.arrive.shared.b64 _, [%0];" :: "r"(addr) : "memory")
#define WAIT_PAR(addr, ph) do {                                                  \
    uint32_t _a = (addr), _p = (ph);                                             \
    asm volatile("{\n\t.reg .pred P;\n\t"                                        \
                 "WL_%=:\n\t"                                                    \
                 "mbarrier.try_wait.parity.shared.b64 P, [%0], %1, 0x989680;\n\t"\
                 "@!P bra WL_%=;\n\t}" :: "r"(_a), "r"(_p) : "memory");          \
} while (0)

#define TMA2D(smem, map, x, y, mbar)                                                          \
    asm volatile("cp.async.bulk.tensor.2d.shared::cta.global.tile.mbarrier::complete_tx::bytes " \
                 "[%0], [%1, {%2, %3}], [%4];"                                                \
                 :: "r"(smem), "l"(map), "r"(x), "r"(y), "r"(mbar) : "memory")

// ld.shared.f32 + round-to-nearest tf32
__device__ __forceinline__ uint32_t lds_tf32(uint32_t addr) {
    uint32_t v;
    asm volatile("{\n\t.reg .f32 f;\n\tld.shared.f32 f, [%1];\n\tcvt.rna.tf32.f32 %0, f;\n\t}"
                 : "=r"(v) : "r"(addr));
    return v;
}

#define MMA_TF32(c, a0, a1, a2, a3, b0, b1)                                      \
    asm volatile("mma.sync.aligned.m16n8k8.row.col.f32.tf32.tf32.f32 "           \
                 "{%0,%1,%2,%3}, {%4,%5,%6,%7}, {%8,%9}, {%0,%1,%2,%3};"         \
                 : "+f"((c)[0]), "+f"((c)[1]), "+f"((c)[2]), "+f"((c)[3])        \
                 : "r"(a0), "r"(a1), "r"(a2), "r"(a3), "r"(b0), "r"(b1))

static constexpr uint32_t STAGES = 3;
static constexpr uint32_t STAGE_BYTES = 32768;      // 16KB A + 16KB B (or 16+8+8)
static constexpr uint32_t SMEM_ASK = STAGES * STAGE_BYTES + 2048;

// ============================================================================
// GEMM2: out = act @ W2^T. CTA 128x128, 4 warps, warp tile 64x64. K = 4096.
// 2 CTAs/SM for decorrelated stalls.
// ============================================================================
__global__ void __launch_bounds__(128, 2) moe_gemm2(
    const __grid_constant__ CUtensorMap tmA,
    const __grid_constant__ CUtensorMap tmB,
    float* __restrict__ out) {
    extern __shared__ __align__(16) char dsm[];
    uint32_t base = (smem_u32(dsm) + 1023u) & ~1023u;
    uint32_t fullb = base + STAGES * STAGE_BYTES;
    uint32_t emptb = fullb + 64;

    int tid = threadIdx.x, wid = tid >> 5, lane = tid & 31;
    int g = lane >> 2, tig = lane & 3;
    int wm = wid >> 1, wn = wid & 1;   // 2x2 warps, warp tile 64x64
    uint32_t xr = (uint32_t)g << 4;

    int b = blockIdx.x;
    int mt = b & 3, nt = (b >> 2) & 15, e = b >> 6;
    int arow = e * NT + mt * 128;
    int brow = e * NH + nt * 128;

    if (tid == 0) {
        for (uint32_t s = 0; s < STAGES; s++) { MBAR_INIT(fullb + 8 * s, 1); MBAR_INIT(emptb + 8 * s, 4); }
        asm volatile("fence.proxy.async.shared::cta;" ::: "memory");
    }
    __syncthreads();

    if (tid == 0) {
        for (uint32_t c = 0; c < STAGES; c++) {
            uint32_t sb = base + c * STAGE_BYTES;
            MBAR_EXPECT_TX(fullb + 8 * c, STAGE_BYTES);
            TMA2D(sb,         &tmA, (int)c * 32, arow, fullb + 8 * c);
            TMA2D(sb + 16384, &tmB, (int)c * 32, brow, fullb + 8 * c);
        }
    }

    float acc[4][8][4];
    #pragma unroll
    for (int i = 0; i < 4; i++)
        #pragma unroll
        for (int j = 0; j < 8; j++)
            #pragma unroll
            for (int q = 0; q < 4; q++) acc[i][j][q] = 0.f;

    uint32_t rowA[4];
    #pragma unroll
    for (int mi = 0; mi < 4; mi++) rowA[mi] = (uint32_t)(wm * 64 + mi * 16 + g) * 128;
    uint32_t rowB = (uint32_t)(wn * 64 + g) * 128;

    int s = 0, ph = 0;
    #pragma unroll 1
    for (int ks = 0; ks < 128; ks++) {
        WAIT_PAR(fullb + 8 * s, ph);
        uint32_t sA = base + (uint32_t)s * STAGE_BYTES;
        uint32_t sB = sA + 16384;

        #pragma unroll
        for (int kk = 0; kk < 4; kk++) {
            uint32_t c0 = (((uint32_t)(kk * 8 + tig)) * 4) ^ xr;
            uint32_t c1 = (((uint32_t)(kk * 8 + tig + 4)) * 4) ^ xr;
            uint32_t a[4][4];
            #pragma unroll
            for (int mi = 0; mi < 4; mi++) {
                a[mi][0] = lds_tf32(sA + rowA[mi] + c0);
                a[mi][1] = lds_tf32(sA + rowA[mi] + 1024 + c0);
                a[mi][2] = lds_tf32(sA + rowA[mi] + c1);
                a[mi][3] = lds_tf32(sA + rowA[mi] + 1024 + c1);
            }
            #pragma unroll
            for (int nj = 0; nj < 8; nj++) {
                uint32_t roff = (uint32_t)nj * 1024;
                uint32_t b0 = lds_tf32(sB + rowB + roff + c0);
                uint32_t b1 = lds_tf32(sB + rowB + roff + c1);
                #pragma unroll
                for (int mi = 0; mi < 4; mi++)
                    MMA_TF32(acc[mi][nj], a[mi][0], a[mi][1], a[mi][2], a[mi][3], b0, b1);
            }
        }
        if (lane == 0) MBAR_ARRIVE(emptb + 8 * s);
        if (tid == 0 && ks + (int)STAGES < 128) {
            WAIT_PAR(emptb + 8 * s, ph);
            uint32_t sb = base + (uint32_t)s * STAGE_BYTES;
            MBAR_EXPECT_TX(fullb + 8 * s, STAGE_BYTES);
            TMA2D(sb,         &tmA, (ks + (int)STAGES) * 32, arow, fullb + 8 * s);
            TMA2D(sb + 16384, &tmB, (ks + (int)STAGES) * 32, brow, fullb + 8 * s);
        }
        if (++s == (int)STAGES) { s = 0; ph ^= 1; }
    }

    #pragma unroll
    for (int mi = 0; mi < 4; mi++) {
        int tok0 = mt * 128 + wm * 64 + mi * 16 + g;
        float* p0 = out + (size_t)(e * NT + tok0) * NH + nt * 128 + wn * 64;
        float* p1 = p0 + (size_t)8 * NH;
        #pragma unroll
        for (int nj = 0; nj < 8; nj++) {
            int colo = nj * 8 + 2 * tig;
            float2 v0 = {acc[mi][nj][0], acc[mi][nj][1]};
            float2 v1 = {acc[mi][nj][2], acc[mi][nj][3]};
            *reinterpret_cast<float2*>(p0 + colo) = v0;
            *reinterpret_cast<float2*>(p1 + colo) = v1;
        }
    }
}

// ============================================================================
// GEMM1: act = up * silu(gate). CTA 128 tokens x 64 act-cols (gate+up fused),
// 4 warps, warp tile 64 x (32 gate + 32 up). 2 CTAs/SM.
// ============================================================================
__global__ void __launch_bounds__(128, 2) moe_gemm1(
    const __grid_constant__ CUtensorMap tmA,
    const __grid_constant__ CUtensorMap tmB) {
    extern __shared__ __align__(16) char dsm[];
    uint32_t base = (smem_u32(dsm) + 1023u) & ~1023u;
    uint32_t fullb = base + STAGES * STAGE_BYTES;
    uint32_t emptb = fullb + 64;

    int tid = threadIdx.x, wid = tid >> 5, lane = tid & 31;
    int g = lane >> 2, tig = lane & 3;
    int wm = wid >> 1, wn = wid & 1;   // warp: 64 tok x (32g + 32u)
    uint32_t xr = (uint32_t)g << 4;

    int b = blockIdx.x;
    int mt = b & 3, nt = (b >> 2) & 63, e = b >> 8;
    int arow = e * NT + mt * 128;
    int grow = e * (2 * NI) + nt * 64;
    int urow = grow + NI;

    if (tid == 0) {
        for (uint32_t s = 0; s < STAGES; s++) { MBAR_INIT(fullb + 8 * s, 1); MBAR_INIT(emptb + 8 * s, 4); }
        asm volatile("fence.proxy.async.shared::cta;" ::: "memory");
    }
    __syncthreads();

    if (tid == 0) {
        for (uint32_t c = 0; c < STAGES; c++) {
            uint32_t sb = base + c * STAGE_BYTES;
            MBAR_EXPECT_TX(fullb + 8 * c, STAGE_BYTES);
            TMA2D(sb,         &tmA, (int)c * 32, arow, fullb + 8 * c);
            TMA2D(sb + 16384, &tmB, (int)c * 32, grow, fullb + 8 * c);
            TMA2D(sb + 24576, &tmB, (int)c * 32, urow, fullb + 8 * c);
        }
    }

    float accg[4][4][4], accu[4][4][4];
    #pragma unroll
    for (int i = 0; i < 4; i++)
        #pragma unroll
        for (int j = 0; j < 4; j++)
            #pragma unroll
            for (int q = 0; q < 4; q++) { accg[i][j][q] = 0.f; accu[i][j][q] = 0.f; }

    uint32_t rowA[4];
    #pragma unroll
    for (int mi = 0; mi < 4; mi++) rowA[mi] = (uint32_t)(wm * 64 + mi * 16 + g) * 128;
    uint32_t rowB = (uint32_t)(wn * 32 + g) * 128;

    int s = 0, ph = 0;
    #pragma unroll 1
    for (int ks = 0; ks < 64; ks++) {
        WAIT_PAR(fullb + 8 * s, ph);
        uint32_t sA  = base + (uint32_t)s * STAGE_BYTES;
        uint32_t sBg = sA + 16384;
        uint32_t sBu = sA + 24576;

        #pragma unroll
        for (int kk = 0; kk < 4; kk++) {
            uint32_t c0 = (((uint32_t)(kk * 8 + tig)) * 4) ^ xr;
            uint32_t c1 = (((uint32_t)(kk * 8 + tig + 4)) * 4) ^ xr;
            uint32_t a[4][4];
            #pragma unroll
            for (int mi = 0; mi < 4; mi++) {
                a[mi][0] = lds_tf32(sA + rowA[mi] + c0);
                a[mi][1] = lds_tf32(sA + rowA[mi] + 1024 + c0);
                a[mi][2] = lds_tf32(sA + rowA[mi] + c1);
                a[mi][3] = lds_tf32(sA + rowA[mi] + 1024 + c1);
            }
            #pragma unroll
            for (int nj = 0; nj < 4; nj++) {
                uint32_t roff = (uint32_t)nj * 1024;
                uint32_t bg0 = lds_tf32(sBg + rowB + roff + c0);
                uint32_t bg1 = lds_tf32(sBg + rowB + roff + c1);
                #pragma unroll
                for (int mi = 0; mi < 4; mi++)
                    MMA_TF32(accg[mi][nj], a[mi][0], a[mi][1], a[mi][2], a[mi][3], bg0, bg1);
                uint32_t bu0 = lds_tf32(sBu + rowB + roff + c0);
                uint32_t bu1 = lds_tf32(sBu + rowB + roff + c1);
                #pragma unroll
                for (int mi = 0; mi < 4; mi++)
                    MMA_TF32(accu[mi][nj], a[mi][0], a[mi][1], a[mi][2], a[mi][3], bu0, bu1);
            }
        }
        if (lane == 0) MBAR_ARRIVE(emptb + 8 * s);
        if (tid == 0 && ks + (int)STAGES < 64) {
            WAIT_PAR(emptb + 8 * s, ph);
            uint32_t sb = base + (uint32_t)s * STAGE_BYTES;
            MBAR_EXPECT_TX(fullb + 8 * s, STAGE_BYTES);
            TMA2D(sb,         &tmA, (ks + (int)STAGES) * 32, arow, fullb + 8 * s);
            TMA2D(sb + 16384, &tmB, (ks + (int)STAGES) * 32, grow, fullb + 8 * s);
            TMA2D(sb + 24576, &tmB, (ks + (int)STAGES) * 32, urow, fullb + 8 * s);
        }
        if (++s == (int)STAGES) { s = 0; ph ^= 1; }
    }

    // Epilogue: SwiGLU in registers -> scratch
    #pragma unroll
    for (int mi = 0; mi < 4; mi++) {
        int tok0 = mt * 128 + wm * 64 + mi * 16 + g;
        float* p0 = g_act + (size_t)(e * NT + tok0) * NI + nt * 64 + wn * 32;
        float* p1 = p0 + (size_t)8 * NI;
        #pragma unroll
        for (int nj = 0; nj < 4; nj++) {
            int colo = nj * 8 + 2 * tig;
            float2 v0, v1;
            float gg = accg[mi][nj][0], uu = accu[mi][nj][0];
            v0.x = uu * gg / (1.0f + __expf(-gg));
            gg = accg[mi][nj][1]; uu = accu[mi][nj][1];
            v0.y = uu * gg / (1.0f + __expf(-gg));
            gg = accg[mi][nj][2]; uu = accu[mi][nj][2];
            v1.x = uu * gg / (1.0f + __expf(-gg));
            gg = accg[mi][nj][3]; uu = accu[mi][nj][3];
            v1.y = uu * gg / (1.0f + __expf(-gg));
            *reinterpret_cast<float2*>(p0 + colo) = v0;
            *reinterpret_cast<float2*>(p1 + colo) = v1;
        }
    }
}

// ============================================================================
// Host
// ============================================================================
typedef CUresult (*EncodeFn)(CUtensorMap*, CUtensorMapDataType, cuuint32_t, void*,
                             const cuuint64_t*, const cuuint64_t*, const cuuint32_t*,
                             const cuuint32_t*, CUtensorMapInterleave, CUtensorMapSwizzle,
                             CUtensorMapL2promotion, CUtensorMapFloatOOBfill);

static void encode2d(EncodeFn fn, CUtensorMap* m, void* p,
                     uint64_t d0, uint64_t d1, uint64_t stride_bytes,
                     uint32_t b0, uint32_t b1) {
    cuuint64_t dims[2] = {d0, d1};
    cuuint64_t st[1]   = {stride_bytes};
    cuuint32_t box[2]  = {b0, b1};
    cuuint32_t es[2]   = {1, 1};
    fn(m, CU_TENSOR_MAP_DATA_TYPE_FLOAT32, 2, p, dims, st, box, es,
       CU_TENSOR_MAP_INTERLEAVE_NONE, CU_TENSOR_MAP_SWIZZLE_128B,
       CU_TENSOR_MAP_L2_PROMOTION_L2_128B, CU_TENSOR_MAP_FLOAT_OOB_FILL_NONE);
}

extern "C" void kernel_launch(void* const* d_in, const int* in_sizes, int n_in,
                              void* d_out, int out_size) {
    void* X  = d_in[0];  // (E*T, H) fp32
    void* W1 = d_in[1];  // (E, 2I, H) fp32
    void* W2 = d_in[2];  // (E, H, I) fp32

    void* pfn = nullptr;
    cudaDriverEntryPointQueryResult qr;
#if CUDART_VERSION >= 12050
    cudaGetDriverEntryPointByVersion("cuTensorMapEncodeTiled", &pfn, 12000,
                                     cudaEnableDefault, &qr);
#else
    cudaGetDriverEntryPoint("cuTensorMapEncodeTiled", &pfn, cudaEnableDefault, &qr);
#endif
    EncodeFn enc = (EncodeFn)pfn;

    void* actp = nullptr;
    cudaGetSymbolAddress(&actp, g_act);

    CUtensorMap tA, tB, tA2, tB2;
    encode2d(enc, &tA,  X,    NH, (uint64_t)NE * NT,     (uint64_t)NH * 4, 32, 128);
    encode2d(enc, &tB,  W1,   NH, (uint64_t)NE * 2 * NI, (uint64_t)NH * 4, 32, 64);
    encode2d(enc, &tA2, actp, NI, (uint64_t)NE * NT,     (uint64_t)NI * 4, 32, 128);
    encode2d(enc, &tB2, W2,   NI, (uint64_t)NE * NH,     (uint64_t)NI * 4, 32, 128);

    cudaFuncSetAttribute(moe_gemm1, cudaFuncAttributeMaxDynamicSharedMemorySize, SMEM_ASK);
    cudaFuncSetAttribute(moe_gemm2, cudaFuncAttributeMaxDynamicSharedMemorySize, SMEM_ASK);

    moe_gemm1<<<NE * 4 * 64, 128, SMEM_ASK>>>(tA, tB);
    moe_gemm2<<<NE * 4 * 16, 128, SMEM_ASK>>>(tA2, tB2, (float*)d_out);
}